// round 17
// baseline (speedup 1.0000x reference)
#include <cuda_runtime.h>
#include <cstdint>

#define DEV_INLINE __device__ __forceinline__

constexpr int N  = 256;
constexpr int T  = 1024;
constexpr int P  = 4;
constexpr int AS = T + P;        // alpha row stride = 1028 floats
constexpr int Tp = T - P;        // 1020

// ---- btl: linear-sweep blocks, block = (i, 8-j-group) x full t ----
constexpr int BTL_BLOCKS = 4192;

// ---- AR partial tiling: (t-group x m-chunk of 16) — R13-proven ----
constexpr int SP_TT   = 16;                      // t per group
constexpr int SP_TG   = 64;                      // 64*16 = 1024 >= 1020
constexpr int SP_MC   = 16;                      // m chunks of 16
constexpr int ARP_BLOCKS = SP_TG * SP_MC;        // 1024
constexpr int CMB_BLOCKS = SP_TG * SP_TT;        // 1024 (one per (tg,tt))

// MEGA: 4192 btl + 1024 arp, 1-in-5 confined interleave + pure-btl tail
constexpr int MEGA_GRID = BTL_BLOCKS + ARP_BLOCKS;   // 5216

__device__ float  g_btl_partial[BTL_BLOCKS];
__device__ double g_ar_partial[CMB_BLOCKS];
__device__ float4 g_phiT4[N * N];                    // phiT4[m][n] = {Phi[k][n][m]}
__device__ float  g_Spart[ARP_BLOCKS * SP_TT * N];   // 16 MB scratch
__device__ int    g_done;                            // last-block counter (reset in pack)

struct SmemBTL {
    float red[8];
};
struct SmemARP {
    float sa[16][20];   // alpha[m0+r][t0+c]
};
union SmemU { SmemBTL b; SmemARP p; };

DEV_INLINE float warpReduce(float v) {
    #pragma unroll
    for (int o = 16; o > 0; o >>= 1)
        v += __shfl_xor_sync(0xffffffffu, v, o);
    return v;
}

DEV_INLINE float blockReduce(float v, float* red) {
    v = warpReduce(v);
    if ((threadIdx.x & 31) == 0) red[threadIdx.x >> 5] = v;
    __syncthreads();
    float r = 0.f;
    if (threadIdx.x < 32) {
        r = (threadIdx.x < 8) ? red[threadIdx.x] : 0.f;
        #pragma unroll
        for (int o = 4; o > 0; o >>= 1)
            r += __shfl_xor_sync(0xffffffffu, r, o);
    }
    __syncthreads();
    return r;
}

// prefix count of btl blocks before row i (analytic)
DEV_INLINE int btl_cum(int i) {
    int m = i >> 3;
    return 32 * i - (4 * m * (m - 1) + (i - 8 * m + 1) * m);
}

DEV_INLINE float4 exp4(float4 v) {
    return make_float4(__expf(v.x), __expf(v.y), __expf(v.z), __expf(v.w));
}

// ---------------- BTL (proven: 67% DRAM, 5.3 TB/s) ----------------
DEV_INLINE void btl_block(const float* __restrict__ Z,
                          const float* __restrict__ W,
                          const float* __restrict__ alpha,
                          SmemBTL& s, int bid) {
    int i = 0;
    #pragma unroll
    for (int step = 128; step > 0; step >>= 1) {
        int cand = i + step;
        if (cand <= 255 && btl_cum(cand) <= bid) i = cand;
    }
    const int jg = ((i + 1) >> 3) + (bid - btl_cum(i));
    const int j0 = jg * 8;
    const bool partial = (j0 <= i);

    const int tid = threadIdx.x;

    const float4* a4 = (const float4*)(alpha);
    const float4 si4 = a4[(i * AS + P) / 4 + tid];
    const float4 ei4 = exp4(si4);

    const float4* Z4 = (const float4*)Z;
    const float4* W4 = (const float4*)W;
    const size_t rowbase = (size_t)(i * N + j0) * (T / 4) + tid;

    float acc0 = 0.f, acc1 = 0.f;

    #pragma unroll
    for (int jb = 0; jb < 8; jb += 2) {
        float4 sjA = a4[((j0 + jb)     * AS + P) / 4 + tid];
        float4 sjB = a4[((j0 + jb + 1) * AS + P) / 4 + tid];

        float4 zA = __ldcs(Z4 + rowbase + (size_t)(jb)     * (T / 4));
        float4 zB = __ldcs(Z4 + rowbase + (size_t)(jb + 1) * (T / 4));
        float4 wA = __ldcs(W4 + rowbase + (size_t)(jb)     * (T / 4));
        float4 wB = __ldcs(W4 + rowbase + (size_t)(jb + 1) * (T / 4));

        float4 lA, lB;
        lA.x = __logf(ei4.x + __expf(sjA.x));
        lA.y = __logf(ei4.y + __expf(sjA.y));
        lA.z = __logf(ei4.z + __expf(sjA.z));
        lA.w = __logf(ei4.w + __expf(sjA.w));
        lB.x = __logf(ei4.x + __expf(sjB.x));
        lB.y = __logf(ei4.y + __expf(sjB.y));
        lB.z = __logf(ei4.z + __expf(sjB.z));
        lB.w = __logf(ei4.w + __expf(sjB.w));

        if (partial) {
            float mA = (j0 + jb     > i) ? 1.f : 0.f;
            float mB = (j0 + jb + 1 > i) ? 1.f : 0.f;
            zA.x *= mA; zA.y *= mA; zA.z *= mA; zA.w *= mA;
            wA.x *= mA; wA.y *= mA; wA.z *= mA; wA.w *= mA;
            zB.x *= mB; zB.y *= mB; zB.z *= mB; zB.w *= mB;
            wB.x *= mB; wB.y *= mB; wB.z *= mB; wB.w *= mB;
        }

        acc0 = fmaf(zA.x, si4.x - lA.x, acc0);
        acc0 = fmaf(zA.y, si4.y - lA.y, acc0);
        acc0 = fmaf(zA.z, si4.z - lA.z, acc0);
        acc0 = fmaf(zA.w, si4.w - lA.w, acc0);
        acc1 = fmaf(wA.x, sjA.x - lA.x, acc1);
        acc1 = fmaf(wA.y, sjA.y - lA.y, acc1);
        acc1 = fmaf(wA.z, sjA.z - lA.z, acc1);
        acc1 = fmaf(wA.w, sjA.w - lA.w, acc1);
        acc0 = fmaf(zB.x, si4.x - lB.x, acc0);
        acc0 = fmaf(zB.y, si4.y - lB.y, acc0);
        acc0 = fmaf(zB.z, si4.z - lB.z, acc0);
        acc0 = fmaf(zB.w, si4.w - lB.w, acc0);
        acc1 = fmaf(wB.x, sjB.x - lB.x, acc1);
        acc1 = fmaf(wB.y, sjB.y - lB.y, acc1);
        acc1 = fmaf(wB.z, sjB.z - lB.z, acc1);
        acc1 = fmaf(wB.w, sjB.w - lB.w, acc1);
    }

    float tot = blockReduce(acc0 + acc1, s.red);
    if (tid == 0) g_btl_partial[bid] = tot;
}

// ---------------- AR partial: (tg, mc of 16 m) -> Spart (R13-proven) ------------
DEV_INLINE void arp_block(const float* __restrict__ alpha,
                          SmemARP& s, int pbid) {
    const int tg = pbid >> 4;          // 0..63
    const int mc = pbid & 15;          // 0..15
    const int t0 = tg * SP_TT;
    const int m0 = mc * 16;
    const int tid = threadIdx.x;       // = n

    // stage alpha[m0+r][t0+c], 320 cells, grid-stride
    #pragma unroll
    for (int idx = tid; idx < 16 * 20; idx += 256) {
        int r = idx / 20, c = idx - r * 20;
        s.sa[r][c] = alpha[(m0 + r) * AS + t0 + c];   // max col 1027 < 1028
    }
    __syncthreads();

    float acc[SP_TT];
    #pragma unroll
    for (int tt = 0; tt < SP_TT; ++tt) acc[tt] = 0.f;

    #pragma unroll 2
    for (int m = 0; m < 16; ++m) {
        float4 p = g_phiT4[(m0 + m) * N + tid];     // coalesced LDG.128, 64 KB/block
        float av[SP_TT + 3];
        #pragma unroll
        for (int c = 0; c < SP_TT + 3; ++c) av[c] = s.sa[m][c];
        #pragma unroll
        for (int tt = 0; tt < SP_TT; ++tt) {
            acc[tt] = fmaf(p.x, av[tt],     acc[tt]);
            acc[tt] = fmaf(p.y, av[tt + 1], acc[tt]);
            acc[tt] = fmaf(p.z, av[tt + 2], acc[tt]);
            acc[tt] = fmaf(p.w, av[tt + 3], acc[tt]);
        }
    }

    float* dst = g_Spart + (size_t)pbid * SP_TT * N + tid;
    #pragma unroll
    for (int tt = 0; tt < SP_TT; ++tt)
        dst[tt * N] = acc[tt];          // coalesced STG.32
}

// ---------------- K0: pack Phi -> phiT4 + reset last-block counter -------------
__global__ __launch_bounds__(256) void pack_kernel(const float* __restrict__ Phi) {
    __shared__ float tile[4][32][33];
    const int mb = blockIdx.x * 32;
    const int nb = blockIdx.y * 32;
    const int tx = threadIdx.x & 31;
    const int ty = threadIdx.x >> 5;   // 0..7

    if (blockIdx.x == 0 && blockIdx.y == 0 && threadIdx.x == 0)
        g_done = 0;                    // reset for this invocation (pre-combine)

    #pragma unroll
    for (int k = 0; k < 4; ++k)
        #pragma unroll
        for (int r = 0; r < 4; ++r)
            tile[k][ty + r * 8][tx] = Phi[(k << 16) + (nb + ty + r * 8) * N + (mb + tx)];
    __syncthreads();

    #pragma unroll
    for (int r = 0; r < 4; ++r) {
        const int ml = ty + r * 8;
        const int nl = tx;
        float4 v = make_float4(tile[0][nl][ml], tile[1][nl][ml],
                               tile[2][nl][ml], tile[3][nl][ml]);
        g_phiT4[(mb + ml) * N + (nb + nl)] = v;
    }
}

// ---------------- MEGA: 4192 btl + 1024 arp, 1-in-5 confined interleave --------
__global__ __launch_bounds__(256, 4) void mega_kernel(const float* __restrict__ Z,
                                                      const float* __restrict__ W,
                                                      const float* __restrict__ alpha) {
    __shared__ SmemU sm;
    const int bid = blockIdx.x;        // grid = 5216
    if (bid < 5120) {
        const int q = bid / 5, r = bid - q * 5;
        if (r == 4) arp_block(alpha, sm.p, q);
        else        btl_block(Z, W, alpha, sm.b, q * 4 + r);
    } else {
        btl_block(Z, W, alpha, sm.b, 4096 + (bid - 5120));
    }
}

// ---------------- Combine + fused finalize (last-block-done) -------------------
__global__ __launch_bounds__(256) void combine_kernel(const float* __restrict__ alpha,
                                                      float* __restrict__ out) {
    __shared__ float red[8];
    __shared__ int   is_last_s;
    const int cb  = blockIdx.x;        // = tg*16 + tt
    const int tg  = cb >> 4;
    const int tt  = cb & 15;
    const int t0  = tg * SP_TT;
    const int tid = threadIdx.x;       // = n

    float S = 0.f;
    const float* sp = g_Spart + ((size_t)(tg * SP_MC) * SP_TT + tt) * N + tid;
    #pragma unroll
    for (int mc = 0; mc < SP_MC; ++mc)
        S += sp[(size_t)mc * SP_TT * N];
    float A = alpha[tid * AS + P + t0 + tt];

    float s1 = blockReduce(S, red);
    float s2 = blockReduce(S * S, red);
    float a1 = blockReduce(A, red);
    float a2 = blockReduce(A * A, red);
    if (tid == 0) {
        double part = 0.0;
        if ((t0 + tt) < Tp) {
            part = (double)N * (double)s2
                 - 2.0 * (double)s1 * (double)a1
                 + (double)N * (double)a2;
        }
        g_ar_partial[cb] = part;
        __threadfence();
        int prev = atomicAdd(&g_done, 1);
        is_last_s = (prev == CMB_BLOCKS - 1) ? 1 : 0;
    }
    __syncthreads();

    if (is_last_s) {
        // fused finalize: fixed-order reduction, single block -> deterministic
        __shared__ double sred[8];
        __shared__ double sred2[8];
        const int lane = tid & 31;
        const int wid  = tid >> 5;

        const float4* p4 = (const float4*)g_btl_partial;
        double s = 0.0;
        #pragma unroll 1
        for (int i2 = tid; i2 < BTL_BLOCKS / 4; i2 += 256) {
            float4 v = p4[i2];
            s += (double)((v.x + v.y) + (v.z + v.w));
        }
        double t2 = 0.0;
        #pragma unroll 1
        for (int i2 = tid; i2 < CMB_BLOCKS; i2 += 256)
            t2 += g_ar_partial[i2];

        #pragma unroll
        for (int o = 16; o > 0; o >>= 1) {
            s  += __shfl_xor_sync(0xffffffffu, s,  o);
            t2 += __shfl_xor_sync(0xffffffffu, t2, o);
        }
        if (lane == 0) { sred[wid] = s; sred2[wid] = t2; }
        __syncthreads();
        if (tid == 0) {
            double a = 0.0, b = 0.0;
            #pragma unroll
            for (int wq = 0; wq < 8; ++wq) { a += sred[wq]; b += sred2[wq]; }
            out[0] = (float)a;
            out[1] = (float)b;
        }
    }
}

extern "C" void kernel_launch(void* const* d_in, const int* in_sizes, int n_in,
                              void* d_out, int out_size) {
    const float* Z     = (const float*)d_in[0];
    const float* W     = (const float*)d_in[1];
    const float* Phi   = (const float*)d_in[2];
    const float* alpha = (const float*)d_in[3];
    float* out = (float*)d_out;

    pack_kernel<<<dim3(8, 8), 256>>>(Phi);
    mega_kernel<<<MEGA_GRID, 256>>>(Z, W, alpha);
    combine_kernel<<<CMB_BLOCKS, 256>>>(alpha, out);
}